// round 2
// baseline (speedup 1.0000x reference)
#include <cuda_runtime.h>
#include <math.h>

// Problem constants (fixed by the reference)
#define NNODES 50000
#define NEDGES 1600000
#define INDIM  512
#define DD1    256
#define DD2    128
#define FEPS   1e-5f

// ---------------- device scratch (static, allowed) ----------------
__device__ int   g_is64;
__device__ int   g_deg[NNODES];
__device__ float g_dis[NNODES];
__device__ int   g_rowoff[NNODES + 1];
__device__ int   g_cursor[NNODES];
__device__ int   g_csr[NEDGES];
__device__ float g_h1[(size_t)NNODES * DD1];
__device__ float g_agg1[(size_t)NNODES * DD1];
__device__ float g_h2[(size_t)NNODES * DD2];
__device__ float g_agg2[(size_t)NNODES * DD2];
__device__ float g_sum1[DD1], g_sq1[DD1], g_scale1[DD1], g_shift1[DD1];
__device__ float g_sum2[DD2], g_sq2[DD2], g_scale2[DD2], g_shift2[DD2];

// ---------------- dtype detection for edge_index ----------------
// If edge_index is int64, the high 32-bit words are all zero (ids < 50000).
// If int32, the odd words are random node ids -> some nonzero.
__global__ void k_detect(const int* __restrict__ e) {
    __shared__ int any;
    if (threadIdx.x == 0) any = 0;
    __syncthreads();
    for (int i = threadIdx.x; i < 1024; i += blockDim.x)
        if (e[2 * i + 1] != 0) any = 1;
    __syncthreads();
    if (threadIdx.x == 0) g_is64 = (any ? 0 : 1);
}

__device__ __forceinline__ int edge_at(const int* __restrict__ e, int idx, int is64) {
    return is64 ? e[2 * (long long)idx] : e[idx];
}

// ---------------- init ----------------
__global__ void k_init() {
    int i = blockIdx.x * blockDim.x + threadIdx.x;
    if (i < NNODES) g_deg[i] = 0;
    if (i < DD1) { g_sum1[i] = 0.f; g_sq1[i] = 0.f; }
    if (i < DD2) { g_sum2[i] = 0.f; g_sq2[i] = 0.f; }
}

// ---------------- degree histogram ----------------
__global__ void k_degree(const int* __restrict__ e) {
    int i = blockIdx.x * blockDim.x + threadIdx.x;
    int is64 = g_is64;
    if (i < NEDGES) {
        int d = edge_at(e, NEDGES + i, is64);
        atomicAdd(&g_deg[d], 1);
    }
}

// ---------------- single-block exclusive scan + dis ----------------
__global__ void k_scan() {
    __shared__ int part[1024];
    int tid = threadIdx.x;
    const int chunk = (NNODES + 1023) / 1024;  // 49
    int start = tid * chunk;
    int end = min(start + chunk, NNODES);
    int s = 0;
    for (int i = start; i < end; i++) s += g_deg[i];
    part[tid] = s;
    __syncthreads();
    // Hillis-Steele inclusive scan
    for (int off = 1; off < 1024; off <<= 1) {
        int v = 0;
        if (tid >= off) v = part[tid - off];
        __syncthreads();
        part[tid] += v;
        __syncthreads();
    }
    int run = (tid > 0) ? part[tid - 1] : 0;
    for (int i = start; i < end; i++) {
        int dgi = g_deg[i];
        g_rowoff[i] = run;
        g_cursor[i] = run;
        run += dgi;
        g_dis[i] = rsqrtf((float)(dgi + 1));  // +1 self loop; always > 0
    }
    if (tid == 1023) g_rowoff[NNODES] = part[1023];
}

// ---------------- CSR bucket scatter ----------------
__global__ void k_scatter(const int* __restrict__ e) {
    int i = blockIdx.x * blockDim.x + threadIdx.x;
    int is64 = g_is64;
    if (i < NEDGES) {
        int s = edge_at(e, i, is64);
        int d = edge_at(e, NEDGES + i, is64);
        int p = atomicAdd(&g_cursor[d], 1);
        g_csr[p] = s;
    }
}

// ---------------- fp32 tiled GEMM: C[M,N] = A[M,K] @ B[K,N] ----------------
// BM=BN=128, BK=8, 256 threads, 8x8 per-thread tile.
// FUSE: A element -> relu(a*scale1[k] + shift1[k])  (BN1 + ReLU fused)
template <bool FUSE, int M, int N, int K>
__device__ __forceinline__ void gemm_impl(const float* __restrict__ A,
                                          const float* __restrict__ B,
                                          float* __restrict__ C) {
    __shared__ float As[8][128];
    __shared__ float Bs[8][128];
    int tid = threadIdx.x;
    int m0 = blockIdx.y * 128;
    int n0 = blockIdx.x * 128;
    int ty = tid >> 4, tx = tid & 15;
    int arow = tid >> 1, acol = (tid & 1) * 4;
    int brow = tid >> 5, bcol = (tid & 31) * 4;

    float acc[8][8];
#pragma unroll
    for (int i = 0; i < 8; i++)
#pragma unroll
        for (int j = 0; j < 8; j++) acc[i][j] = 0.f;

    for (int k0 = 0; k0 < K; k0 += 8) {
        float4 av = make_float4(0.f, 0.f, 0.f, 0.f);
        int gr = m0 + arow;
        if (gr < M) {
            av = *(const float4*)(A + (size_t)gr * K + k0 + acol);
            if (FUSE) {
                int c = k0 + acol;
                av.x = fmaxf(av.x * g_scale1[c + 0] + g_shift1[c + 0], 0.f);
                av.y = fmaxf(av.y * g_scale1[c + 1] + g_shift1[c + 1], 0.f);
                av.z = fmaxf(av.z * g_scale1[c + 2] + g_shift1[c + 2], 0.f);
                av.w = fmaxf(av.w * g_scale1[c + 3] + g_shift1[c + 3], 0.f);
            }
        }
        float4 bv = *(const float4*)(B + (size_t)(k0 + brow) * N + n0 + bcol);

        As[acol + 0][arow] = av.x;
        As[acol + 1][arow] = av.y;
        As[acol + 2][arow] = av.z;
        As[acol + 3][arow] = av.w;
        *(float4*)&Bs[brow][bcol] = bv;
        __syncthreads();

#pragma unroll
        for (int kk = 0; kk < 8; kk++) {
            float a[8], b[8];
            *(float4*)&a[0] = *(const float4*)&As[kk][ty * 8];
            *(float4*)&a[4] = *(const float4*)&As[kk][ty * 8 + 4];
            *(float4*)&b[0] = *(const float4*)&Bs[kk][tx * 8];
            *(float4*)&b[4] = *(const float4*)&Bs[kk][tx * 8 + 4];
#pragma unroll
            for (int i = 0; i < 8; i++)
#pragma unroll
                for (int j = 0; j < 8; j++) acc[i][j] += a[i] * b[j];
        }
        __syncthreads();
    }

#pragma unroll
    for (int i = 0; i < 8; i++) {
        int gr = m0 + ty * 8 + i;
        if (gr < M) {
            float4 v0 = make_float4(acc[i][0], acc[i][1], acc[i][2], acc[i][3]);
            float4 v1 = make_float4(acc[i][4], acc[i][5], acc[i][6], acc[i][7]);
            *(float4*)(C + (size_t)gr * N + n0 + tx * 8) = v0;
            *(float4*)(C + (size_t)gr * N + n0 + tx * 8 + 4) = v1;
        }
    }
}

__global__ __launch_bounds__(256) void k_gemm1(const float* __restrict__ A,
                                               const float* __restrict__ B) {
    gemm_impl<false, NNODES, DD1, INDIM>(A, B, g_h1);
}
__global__ __launch_bounds__(256) void k_gemm2(const float* __restrict__ B) {
    gemm_impl<true, NNODES, DD2, DD1>(g_agg1, B, g_h2);
}

// ---------------- gather aggregation: out[d] = dis[d]*(dis[d]*h[d] + sum dis[s]*h[s]) ----------------
template <int DIM>
__device__ __forceinline__ void agg_impl(const float* __restrict__ H, float* __restrict__ O) {
    int d = blockIdx.x;
    int t = threadIdx.x;
    float dd = g_dis[d];
    float acc = dd * H[(size_t)d * DIM + t];
    int beg = g_rowoff[d], end = g_rowoff[d + 1];
    __shared__ int ss[128];
    __shared__ float sw[128];
    for (int base = beg; base < end; base += 128) {
        int cnt = min(end - base, 128);
        __syncthreads();
        if (t < cnt) {
            int s = g_csr[base + t];
            ss[t] = s;
            sw[t] = g_dis[s];
        }
        __syncthreads();
#pragma unroll 4
        for (int j = 0; j < cnt; j++)
            acc += sw[j] * H[(size_t)ss[j] * DIM + t];
    }
    O[(size_t)d * DIM + t] = acc * dd;
}

__global__ void k_agg1() { agg_impl<DD1>(g_h1, g_agg1); }
__global__ void k_agg2() { agg_impl<DD2>(g_h2, g_agg2); }

// ---------------- BN stats (two-pass: sum / sumsq) ----------------
template <int DIM>
__device__ __forceinline__ void bnstats_impl(const float* __restrict__ X,
                                             float* __restrict__ sum,
                                             float* __restrict__ sq) {
    int t = threadIdx.x;
    int r0 = blockIdx.x * 64;
    int r1 = min(r0 + 64, NNODES);
    float s = 0.f, q = 0.f;
    for (int r = r0; r < r1; r++) {
        float v = X[(size_t)r * DIM + t];
        s += v;
        q += v * v;
    }
    atomicAdd(&sum[t], s);
    atomicAdd(&sq[t], q);
}
__global__ void k_bnstats1() { bnstats_impl<DD1>(g_agg1, g_sum1, g_sq1); }
__global__ void k_bnstats2() { bnstats_impl<DD2>(g_agg2, g_sum2, g_sq2); }

template <int DIM>
__device__ __forceinline__ void finalize_impl(const float* __restrict__ sum,
                                              const float* __restrict__ sq,
                                              const float* __restrict__ gamma,
                                              const float* __restrict__ beta,
                                              float* __restrict__ scale,
                                              float* __restrict__ shift) {
    int t = threadIdx.x;
    float mean = sum[t] * (1.f / NNODES);
    float var = fmaxf(sq[t] * (1.f / NNODES) - mean * mean, 0.f);
    float inv = rsqrtf(var + FEPS);
    float sc = inv * gamma[t];
    scale[t] = sc;
    shift[t] = beta[t] - mean * sc;
}
__global__ void k_finalize1(const float* g, const float* b) {
    finalize_impl<DD1>(g_sum1, g_sq1, g, b, g_scale1, g_shift1);
}
__global__ void k_finalize2(const float* g, const float* b) {
    finalize_impl<DD2>(g_sum2, g_sq2, g, b, g_scale2, g_shift2);
}

// ---------------- final BN2 apply -> d_out ----------------
__global__ void k_apply(float* __restrict__ out) {
    int i = blockIdx.x * blockDim.x + threadIdx.x;
    if (i < NNODES * DD2) {
        int c = i & (DD2 - 1);
        out[i] = g_agg2[i] * g_scale2[c] + g_shift2[c];
    }
}

// ---------------- launch ----------------
extern "C" void kernel_launch(void* const* d_in, const int* in_sizes, int n_in,
                              void* d_out, int out_size) {
    const float* x      = (const float*)d_in[0];
    const int*   e      = (const int*)d_in[1];   // int32 or int64, detected at runtime
    const float* W1     = (const float*)d_in[2];
    // d_in[3] = b1: cancels under BatchNorm, unused
    const float* gamma1 = (const float*)d_in[4];
    const float* beta1  = (const float*)d_in[5];
    const float* W2     = (const float*)d_in[6];
    // d_in[7] = b2: cancels under BatchNorm, unused
    const float* gamma2 = (const float*)d_in[8];
    const float* beta2  = (const float*)d_in[9];
    float* out = (float*)d_out;

    const int EG = (NEDGES + 255) / 256;

    k_detect<<<1, 256>>>(e);
    k_init<<<(NNODES + 255) / 256, 256>>>();
    k_degree<<<EG, 256>>>(e);
    k_scan<<<1, 1024>>>();
    k_scatter<<<EG, 256>>>(e);

    k_gemm1<<<dim3(DD1 / 128, (NNODES + 127) / 128), 256>>>(x, W1);
    k_agg1<<<NNODES, 256>>>();
    k_bnstats1<<<(NNODES + 63) / 64, DD1>>>();
    k_finalize1<<<1, DD1>>>(gamma1, beta1);

    k_gemm2<<<dim3(DD2 / 128, (NNODES + 127) / 128), 256>>>(W2);
    k_agg2<<<NNODES, 128>>>();
    k_bnstats2<<<(NNODES + 63) / 64, DD2>>>();
    k_finalize2<<<1, DD2>>>(gamma2, beta2);

    k_apply<<<(NNODES * DD2 + 255) / 256, 256>>>(out);
}

// round 5
// speedup vs baseline: 1.0931x; 1.0931x over previous
#include <cuda_runtime.h>
#include <cuda_bf16.h>
#include <math.h>
#include <stdint.h>

// Problem constants (fixed by the reference)
#define NNODES 50000
#define NEDGES 1600000
#define INDIM  512
#define DD1    256
#define DD2    128
#define FEPS   1e-5f
#define SCANB  ((NNODES + 255) / 256)   // 196

// ---------------- device scratch ----------------
__device__ int   g_is64;
__device__ int   g_deg[NNODES];
__device__ float g_dis[NNODES];
__device__ int   g_rowoff[NNODES + 1];
__device__ int   g_cursor[NNODES];
__device__ int   g_csr[NEDGES];
__device__ int   g_bsum[SCANB];
__device__ int   g_bpre[SCANB];
__device__ float g_h1[(size_t)NNODES * DD1];
__device__ float g_agg1[(size_t)NNODES * DD1];
__device__ float g_h2[(size_t)NNODES * DD2];
__device__ float g_agg2[(size_t)NNODES * DD2];
__device__ float g_sum1[DD1], g_sq1[DD1], g_scale1[DD1], g_shift1[DD1];
__device__ float g_sum2[DD2], g_sq2[DD2], g_scale2[DD2], g_shift2[DD2];

// ---------------- helpers ----------------
__device__ __forceinline__ uint32_t smem_u32(const void* p) {
    uint32_t a;
    asm("{ .reg .u64 t; cvta.to.shared.u64 t, %1; cvt.u32.u64 %0, t; }" : "=r"(a) : "l"(p));
    return a;
}

// split fp32 -> bf16 hi + bf16(residual)
__device__ __forceinline__ uint32_t pack_split(float a, float b, float& ra, float& rb) {
    __nv_bfloat16 ha = __float2bfloat16(a);
    __nv_bfloat16 hb = __float2bfloat16(b);
    ra = a - __bfloat162float(ha);
    rb = b - __bfloat162float(hb);
    return (uint32_t)__bfloat16_as_ushort(ha) | ((uint32_t)__bfloat16_as_ushort(hb) << 16);
}
__device__ __forceinline__ uint32_t pack_bf2(float a, float b) {
    return (uint32_t)__bfloat16_as_ushort(__float2bfloat16(a)) |
           ((uint32_t)__bfloat16_as_ushort(__float2bfloat16(b)) << 16);
}

#define LDSM_X4(f, addr) \
    asm volatile("ldmatrix.sync.aligned.m8n8.x4.shared.b16 {%0,%1,%2,%3}, [%4];" \
        : "=r"((f)[0]), "=r"((f)[1]), "=r"((f)[2]), "=r"((f)[3]) : "r"(addr))

#define MMA_BF16(c, a, b0, b1) \
    asm volatile("mma.sync.aligned.m16n8k16.row.col.f32.bf16.bf16.f32 " \
        "{%0,%1,%2,%3}, {%4,%5,%6,%7}, {%8,%9}, {%0,%1,%2,%3};" \
        : "+f"((c)[0]), "+f"((c)[1]), "+f"((c)[2]), "+f"((c)[3]) \
        : "r"((a)[0]), "r"((a)[1]), "r"((a)[2]), "r"((a)[3]), "r"(b0), "r"(b1))

// ---------------- edge dtype detection ----------------
__global__ void k_detect(const int* __restrict__ e) {
    __shared__ int any;
    if (threadIdx.x == 0) any = 0;
    __syncthreads();
    for (int i = threadIdx.x; i < 1024; i += blockDim.x)
        if (e[2 * i + 1] != 0) any = 1;
    __syncthreads();
    if (threadIdx.x == 0) g_is64 = (any ? 0 : 1);
}
__device__ __forceinline__ int edge_at(const int* __restrict__ e, int idx, int is64) {
    return is64 ? e[2 * (long long)idx] : e[idx];
}

// ---------------- init ----------------
__global__ void k_init() {
    int i = blockIdx.x * blockDim.x + threadIdx.x;
    if (i < NNODES) g_deg[i] = 0;
    if (i < DD1) { g_sum1[i] = 0.f; g_sq1[i] = 0.f; }
    if (i < DD2) { g_sum2[i] = 0.f; g_sq2[i] = 0.f; }
    if (i == 0) g_rowoff[NNODES] = NEDGES;
}

// ---------------- degree histogram ----------------
__global__ void k_degree(const int* __restrict__ e) {
    int i = blockIdx.x * blockDim.x + threadIdx.x;
    int is64 = g_is64;
    if (i < NEDGES) atomicAdd(&g_deg[edge_at(e, NEDGES + i, is64)], 1);
}

// ---------------- hierarchical scan (3 kernels) ----------------
__global__ void k_scan_a() {
    __shared__ int red[256];
    int t = threadIdx.x;
    int i = blockIdx.x * 256 + t;
    int d = (i < NNODES) ? g_deg[i] : 0;
    if (i < NNODES) g_dis[i] = rsqrtf((float)(d + 1));
    red[t] = d;
    __syncthreads();
    for (int off = 128; off > 0; off >>= 1) {
        if (t < off) red[t] += red[t + off];
        __syncthreads();
    }
    if (t == 0) g_bsum[blockIdx.x] = red[0];
}
__global__ void k_scan_b() {
    __shared__ int s[256];
    int t = threadIdx.x;
    int v = (t < SCANB) ? g_bsum[t] : 0;
    s[t] = v;
    __syncthreads();
    for (int off = 1; off < 256; off <<= 1) {
        int u = (t >= off) ? s[t - off] : 0;
        __syncthreads();
        s[t] += u;
        __syncthreads();
    }
    if (t < SCANB) g_bpre[t] = s[t] - v;   // exclusive
}
__global__ void k_scan_c() {
    __shared__ int s[256];
    int t = threadIdx.x;
    int i = blockIdx.x * 256 + t;
    int d = (i < NNODES) ? g_deg[i] : 0;
    s[t] = d;
    __syncthreads();
    for (int off = 1; off < 256; off <<= 1) {
        int u = (t >= off) ? s[t - off] : 0;
        __syncthreads();
        s[t] += u;
        __syncthreads();
    }
    if (i < NNODES) {
        int excl = s[t] - d + g_bpre[blockIdx.x];
        g_rowoff[i] = excl;
        g_cursor[i] = excl;
    }
}

// ---------------- CSR bucket scatter ----------------
__global__ void k_scatter(const int* __restrict__ e) {
    int i = blockIdx.x * blockDim.x + threadIdx.x;
    int is64 = g_is64;
    if (i < NEDGES) {
        int s = edge_at(e, i, is64);
        int d = edge_at(e, NEDGES + i, is64);
        g_csr[atomicAdd(&g_cursor[d], 1)] = s;
    }
}

// ---------------- mma.sync split-bf16 GEMM ----------------
// C[M,NT] block tile 128x128 = A[M,Ktot] @ B[Ktot,NT]; D = Ah*Bh + Ah*Bl + Al*Bh
// 256 threads = 8 warps (4 m x 2 n), warp tile 32x64, BK=32.
// SMEM: padded row stride 40 bf16 (80 B, 16B-aligned, conflict-free for ldmatrix).
// FUSE: A element -> relu(a*scale1[k] + shift1[k])  (BN1+ReLU fused into gemm2 A-load)
#define ASTRIDE 40
template <bool FUSE>
__global__ __launch_bounds__(256) void k_mgemm(const float* __restrict__ A,
                                               const float* __restrict__ B,
                                               float* __restrict__ C,
                                               int Ktot, int NT) {
    __shared__ __align__(16) __nv_bfloat16 As_h[128 * ASTRIDE];
    __shared__ __align__(16) __nv_bfloat16 As_l[128 * ASTRIDE];
    __shared__ __align__(16) __nv_bfloat16 Bs_h[128 * ASTRIDE];
    __shared__ __align__(16) __nv_bfloat16 Bs_l[128 * ASTRIDE];

    int tid = threadIdx.x, wid = tid >> 5, l = tid & 31;
    int m0 = blockIdx.y * 128, n0 = blockIdx.x * 128;
    int wm = wid & 3, wn = wid >> 2;

    uint32_t bAh = smem_u32(As_h), bAl = smem_u32(As_l);
    uint32_t bBh = smem_u32(Bs_h), bBl = smem_u32(Bs_l);

    // A loader mapping: 2 threads/row, 16 floats each
    int arow = tid >> 1, acb = (tid & 1) * 16;
    int gr = m0 + arow; if (gr > NNODES - 1) gr = NNODES - 1;  // clamp, tail discarded
    const float* Arow = A + (size_t)gr * Ktot;
    // B loader mapping
    int bk = tid >> 5, bn4 = (tid & 31) * 4;

    float acc[2][8][4];
#pragma unroll
    for (int a = 0; a < 2; a++)
#pragma unroll
        for (int b = 0; b < 8; b++)
#pragma unroll
            for (int c = 0; c < 4; c++) acc[a][b][c] = 0.f;

    // ldmatrix lane addresses (fixed per thread)
    int a_r = (l & 7) + ((l >> 3) & 1) * 8;          // row within 16
    int a_c = ((l >> 4) & 1) * 8;                     // col 0/8
    int b_n = (l & 7) + ((l >> 4) & 1) * 8;          // n within 16
    int b_k = ((l >> 3) & 1) * 8;                     // k 0/8

    for (int k0 = 0; k0 < Ktot; k0 += 32) {
        // ---- stage A 128x32 ----
#pragma unroll
        for (int q = 0; q < 4; q++) {
            int c = acb + q * 4;
            float4 v = *(const float4*)(Arow + k0 + c);
            if (FUSE) {
                int cc = k0 + c;
                v.x = fmaxf(fmaf(v.x, g_scale1[cc + 0], g_shift1[cc + 0]), 0.f);
                v.y = fmaxf(fmaf(v.y, g_scale1[cc + 1], g_shift1[cc + 1]), 0.f);
                v.z = fmaxf(fmaf(v.z, g_scale1[cc + 2], g_shift1[cc + 2]), 0.f);
                v.w = fmaxf(fmaf(v.w, g_scale1[cc + 3], g_shift1[cc + 3]), 0.f);
            }
            float r0, r1, r2, r3;
            uint32_t h01 = pack_split(v.x, v.y, r0, r1);
            uint32_t h23 = pack_split(v.z, v.w, r2, r3);
            int off = arow * ASTRIDE + c;
            *(uint2*)(As_h + off) = make_uint2(h01, h23);
            *(uint2*)(As_l + off) = make_uint2(pack_bf2(r0, r1), pack_bf2(r2, r3));
        }
        // ---- stage B 32(k) x 128(n), transposed to [n][k] ----
#pragma unroll
        for (int kk2 = 0; kk2 < 4; kk2++) {
            int kr = bk + kk2 * 8;
            float4 v = *(const float4*)(B + (size_t)(k0 + kr) * NT + n0 + bn4);
            float vv[4] = {v.x, v.y, v.z, v.w};
#pragma unroll
            for (int j = 0; j < 4; j++) {
                __nv_bfloat16 h = __float2bfloat16(vv[j]);
                float rr = vv[j] - __bfloat162float(h);
                Bs_h[(bn4 + j) * ASTRIDE + kr] = h;
                Bs_l[(bn4 + j) * ASTRIDE + kr] = __float2bfloat16(rr);
            }
        }
        __syncthreads();

        // ---- compute: 2 k16 sub-steps ----
#pragma unroll
        for (int kk = 0; kk < 32; kk += 16) {
            uint32_t ah[2][4], al[2][4];
#pragma unroll
            for (int mi = 0; mi < 2; mi++) {
                int r = wm * 32 + mi * 16 + a_r;
                uint32_t off = (uint32_t)(r * (ASTRIDE * 2) + (kk + a_c) * 2);
                LDSM_X4(ah[mi], bAh + off);
                LDSM_X4(al[mi], bAl + off);
            }
#pragma unroll
            for (int ng = 0; ng < 4; ng++) {
                uint32_t bh[4], bl[4];
                int nr = wn * 64 + ng * 16 + b_n;
                uint32_t off = (uint32_t)(nr * (ASTRIDE * 2) + (kk + b_k) * 2);
                LDSM_X4(bh, bBh + off);
                LDSM_X4(bl, bBl + off);
#pragma unroll
                for (int mi = 0; mi < 2; mi++) {
                    MMA_BF16(acc[mi][ng * 2 + 0], ah[mi], bh[0], bh[1]);
                    MMA_BF16(acc[mi][ng * 2 + 0], ah[mi], bl[0], bl[1]);
                    MMA_BF16(acc[mi][ng * 2 + 0], al[mi], bh[0], bh[1]);
                    MMA_BF16(acc[mi][ng * 2 + 1], ah[mi], bh[2], bh[3]);
                    MMA_BF16(acc[mi][ng * 2 + 1], ah[mi], bl[2], bl[3]);
                    MMA_BF16(acc[mi][ng * 2 + 1], al[mi], bh[2], bh[3]);
                }
            }
        }
        __syncthreads();
    }

    // ---- epilogue ----
#pragma unroll
    for (int mi = 0; mi < 2; mi++) {
#pragma unroll
        for (int ni = 0; ni < 8; ni++) {
            int r = m0 + wm * 32 + mi * 16 + (l >> 2);
            int cc = n0 + wn * 64 + ni * 8 + (l & 3) * 2;
            if (r < NNODES)
                *(float2*)(C + (size_t)r * NT + cc) = make_float2(acc[mi][ni][0], acc[mi][ni][1]);
            if (r + 8 < NNODES)
                *(float2*)(C + (size_t)(r + 8) * NT + cc) = make_float2(acc[mi][ni][2], acc[mi][ni][3]);
        }
    }
}

// ---------------- gather aggregation ----------------
template <int DIM>
__device__ __forceinline__ void agg_impl(const float* __restrict__ H, float* __restrict__ O) {
    int d = blockIdx.x;
    int t = threadIdx.x;
    float dd = g_dis[d];
    float acc = dd * H[(size_t)d * DIM + t];
    int beg = g_rowoff[d], end = g_rowoff[d + 1];
    __shared__ int ss[128];
    __shared__ float sw[128];
    for (int base = beg; base < end; base += 128) {
        int cnt = min(end - base, 128);
        __syncthreads();
        if (t < cnt) {
            int s = g_csr[base + t];
            ss[t] = s;
            sw[t] = g_dis[s];
        }
        __syncthreads();
#pragma unroll 4
        for (int j = 0; j < cnt; j++)
            acc += sw[j] * H[(size_t)ss[j] * DIM + t];
    }
    O[(size_t)d * DIM + t] = acc * dd;
}
__global__ void k_agg1() { agg_impl<DD1>(g_h1, g_agg1); }
__global__ void k_agg2() { agg_impl<DD2>(g_h2, g_agg2); }

// ---------------- BN stats ----------------
template <int DIM>
__device__ __forceinline__ void bnstats_impl(const float* __restrict__ X,
                                             float* __restrict__ sum, float* __restrict__ sq) {
    int t = threadIdx.x;
    int r0 = blockIdx.x * 64;
    int r1 = min(r0 + 64, NNODES);
    float s = 0.f, q = 0.f;
    for (int r = r0; r < r1; r++) {
        float v = X[(size_t)r * DIM + t];
        s += v;
        q += v * v;
    }
    atomicAdd(&sum[t], s);
    atomicAdd(&sq[t], q);
}
__global__ void k_bnstats1() { bnstats_impl<DD1>(g_agg1, g_sum1, g_sq1); }
__global__ void k_bnstats2() { bnstats_impl<DD2>(g_agg2, g_sum2, g_sq2); }

template <int DIM>
__device__ __forceinline__ void finalize_impl(const float* __restrict__ sum,
                                              const float* __restrict__ sq,
                                              const float* __restrict__ gamma,
                                              const float* __restrict__ beta,
                                              float* __restrict__ scale,
                                              float* __restrict__ shift) {
    int t = threadIdx.x;
    float mean = sum[t] * (1.f / NNODES);
    float var = fmaxf(sq[t] * (1.f / NNODES) - mean * mean, 0.f);
    float sc = rsqrtf(var + FEPS) * gamma[t];
    scale[t] = sc;
    shift[t] = beta[t] - mean * sc;
}
__global__ void k_finalize1(const float* g, const float* b) {
    finalize_impl<DD1>(g_sum1, g_sq1, g, b, g_scale1, g_shift1);
}
__global__ void k_finalize2(const float* g, const float* b) {
    finalize_impl<DD2>(g_sum2, g_sq2, g, b, g_scale2, g_shift2);
}

// ---------------- final BN2 apply -> d_out ----------------
__global__ void k_apply(float* __restrict__ out) {
    int i = blockIdx.x * blockDim.x + threadIdx.x;
    if (i < NNODES * DD2) {
        int c = i & (DD2 - 1);
        out[i] = g_agg2[i] * g_scale2[c] + g_shift2[c];
    }
}

// ---------------- launch ----------------
extern "C" void kernel_launch(void* const* d_in, const int* in_sizes, int n_in,
                              void* d_out, int out_size) {
    const float* x      = (const float*)d_in[0];
    const int*   e      = (const int*)d_in[1];
    const float* W1     = (const float*)d_in[2];
    const float* gamma1 = (const float*)d_in[4];
    const float* beta1  = (const float*)d_in[5];
    const float* W2     = (const float*)d_in[6];
    const float* gamma2 = (const float*)d_in[8];
    const float* beta2  = (const float*)d_in[9];
    float* out = (float*)d_out;

    void *p_h1, *p_agg1, *p_h2;
    cudaGetSymbolAddress(&p_h1, g_h1);
    cudaGetSymbolAddress(&p_agg1, g_agg1);
    cudaGetSymbolAddress(&p_h2, g_h2);

    const int EG = (NEDGES + 255) / 256;
    const int MB = (NNODES + 127) / 128;   // 391

    k_detect<<<1, 256>>>(e);
    k_init<<<(NNODES + 255) / 256, 256>>>();
    k_degree<<<EG, 256>>>(e);
    k_scan_a<<<SCANB, 256>>>();
    k_scan_b<<<1, 256>>>();
    k_scan_c<<<SCANB, 256>>>();
    k_scatter<<<EG, 256>>>(e);

    k_mgemm<false><<<dim3(2, MB), 256>>>(x, W1, (float*)p_h1, INDIM, DD1);
    k_agg1<<<NNODES, 256>>>();
    k_bnstats1<<<(NNODES + 63) / 64, DD1>>>();
    k_finalize1<<<1, DD1>>>(gamma1, beta1);

    k_mgemm<true><<<dim3(1, MB), 256>>>((const float*)p_agg1, W2, (float*)p_h2, DD1, DD2);
    k_agg2<<<NNODES, 128>>>();
    k_bnstats2<<<(NNODES + 63) / 64, DD2>>>();
    k_finalize2<<<1, DD2>>>(gamma2, beta2);

    k_apply<<<(NNODES * DD2 + 255) / 256, 256>>>(out);
}

// round 7
// speedup vs baseline: 1.7765x; 1.6252x over previous
#include <cuda_runtime.h>
#include <cuda_bf16.h>
#include <math.h>
#include <stdint.h>

#define NNODES 50000
#define NEDGES 1600000
#define INDIM  512
#define DD1    256
#define DD2    128
#define FEPS   1e-5f
#define SCANB  ((NNODES + 255) / 256)   // 196

// ---------------- device scratch ----------------
__device__ int   g_is64;
__device__ int   g_deg[NNODES];
__device__ float g_dis[NNODES];
__device__ int   g_rowoff[NNODES + 1];
__device__ int   g_cursor[NNODES];
__device__ int   g_csr[NEDGES];
__device__ int   g_bsum[SCANB];
__device__ int   g_bpre[SCANB];
__device__ __nv_bfloat16 g_xh[(size_t)NNODES * INDIM];
__device__ __nv_bfloat16 g_xl[(size_t)NNODES * INDIM];
__device__ __nv_bfloat16 g_w1ht[DD1 * INDIM];   // [n][k] transposed
__device__ __nv_bfloat16 g_w1lt[DD1 * INDIM];
__device__ __nv_bfloat16 g_w2ht[DD2 * DD1];
__device__ __nv_bfloat16 g_w2lt[DD2 * DD1];
__device__ float g_h1[(size_t)NNODES * DD1];
__device__ float g_agg1[(size_t)NNODES * DD1];
__device__ float g_h2[(size_t)NNODES * DD2];
__device__ float g_agg2[(size_t)NNODES * DD2];
__device__ float g_sum1[DD1], g_sq1[DD1], g_scale1[DD1], g_shift1[DD1];
__device__ float g_sum2[DD2], g_sq2[DD2], g_scale2[DD2], g_shift2[DD2];

// ---------------- helpers ----------------
__device__ __forceinline__ uint32_t smem_u32(const void* p) {
    uint32_t a;
    asm("{ .reg .u64 t; cvta.to.shared.u64 t, %1; cvt.u32.u64 %0, t; }" : "=r"(a) : "l"(p));
    return a;
}
__device__ __forceinline__ uint32_t pack_split(float a, float b, float& ra, float& rb) {
    __nv_bfloat16 ha = __float2bfloat16(a);
    __nv_bfloat16 hb = __float2bfloat16(b);
    ra = a - __bfloat162float(ha);
    rb = b - __bfloat162float(hb);
    return (uint32_t)__bfloat16_as_ushort(ha) | ((uint32_t)__bfloat16_as_ushort(hb) << 16);
}
__device__ __forceinline__ uint32_t pack_bf2(float a, float b) {
    return (uint32_t)__bfloat16_as_ushort(__float2bfloat16(a)) |
           ((uint32_t)__bfloat16_as_ushort(__float2bfloat16(b)) << 16);
}

#define LDSM_X4(f, addr) \
    asm volatile("ldmatrix.sync.aligned.m8n8.x4.shared.b16 {%0,%1,%2,%3}, [%4];" \
        : "=r"((f)[0]), "=r"((f)[1]), "=r"((f)[2]), "=r"((f)[3]) : "r"(addr))

#define MMA_BF16(c, a, b0, b1) \
    asm volatile("mma.sync.aligned.m16n8k16.row.col.f32.bf16.bf16.f32 " \
        "{%0,%1,%2,%3}, {%4,%5,%6,%7}, {%8,%9}, {%0,%1,%2,%3};" \
        : "+f"((c)[0]), "+f"((c)[1]), "+f"((c)[2]), "+f"((c)[3]) \
        : "r"((a)[0]), "r"((a)[1]), "r"((a)[2]), "r"((a)[3]), "r"(b0), "r"(b1))

#define ASTRIDE 40   // bf16 elements per smem row (80B, 16B aligned, ldsm conflict-free)

// ---------------- init (+ edge dtype detect in block 0) ----------------
__global__ void k_init(const int* __restrict__ e) {
    int i = blockIdx.x * blockDim.x + threadIdx.x;
    if (i < NNODES) g_deg[i] = 0;
    if (i < DD1) { g_sum1[i] = 0.f; g_sq1[i] = 0.f; }
    if (i < DD2) { g_sum2[i] = 0.f; g_sq2[i] = 0.f; }
    if (i == 0) g_rowoff[NNODES] = NEDGES;
    if (blockIdx.x == 0) {
        __shared__ int any;
        if (threadIdx.x == 0) any = 0;
        __syncthreads();
        for (int j = threadIdx.x; j < 1024; j += blockDim.x)
            if (e[2 * j + 1] != 0) any = 1;
        __syncthreads();
        if (threadIdx.x == 0) g_is64 = (any ? 0 : 1);
    }
}
__device__ __forceinline__ int edge_at(const int* __restrict__ e, int idx, int is64) {
    return is64 ? e[2 * (long long)idx] : e[idx];
}

// ---------------- pre-split kernels ----------------
__global__ void k_split_x(const float* __restrict__ x) {
    size_t i = (size_t)blockIdx.x * blockDim.x + threadIdx.x;
    if (i < (size_t)NNODES * INDIM / 4) {
        float4 v = ((const float4*)x)[i];
        float r0, r1, r2, r3;
        uint32_t h01 = pack_split(v.x, v.y, r0, r1);
        uint32_t h23 = pack_split(v.z, v.w, r2, r3);
        ((uint2*)g_xh)[i] = make_uint2(h01, h23);
        ((uint2*)g_xl)[i] = make_uint2(pack_bf2(r0, r1), pack_bf2(r2, r3));
    }
}
__global__ void k_split_w1(const float* __restrict__ W1) {
    int i = blockIdx.x * blockDim.x + threadIdx.x;   // < 256*512
    if (i < DD1 * INDIM) {
        int k = i & (INDIM - 1), n = i >> 9;
        float v = W1[k * DD1 + n];
        __nv_bfloat16 h = __float2bfloat16(v);
        g_w1ht[i] = h;
        g_w1lt[i] = __float2bfloat16(v - __bfloat162float(h));
    }
}
__global__ void k_split_w2(const float* __restrict__ W2) {
    int i = blockIdx.x * blockDim.x + threadIdx.x;   // < 128*256
    if (i < DD2 * DD1) {
        int k = i & (DD1 - 1), n = i >> 8;
        float v = W2[k * DD2 + n];
        __nv_bfloat16 h = __float2bfloat16(v);
        g_w2ht[i] = h;
        g_w2lt[i] = __float2bfloat16(v - __bfloat162float(h));
    }
}

// ---------------- degree histogram ----------------
__global__ void k_degree(const int* __restrict__ e) {
    int i = blockIdx.x * blockDim.x + threadIdx.x;
    int is64 = g_is64;
    if (i < NEDGES) atomicAdd(&g_deg[edge_at(e, NEDGES + i, is64)], 1);
}

// ---------------- hierarchical scan ----------------
__global__ void k_scan_a() {
    __shared__ int red[256];
    int t = threadIdx.x;
    int i = blockIdx.x * 256 + t;
    int d = (i < NNODES) ? g_deg[i] : 0;
    if (i < NNODES) g_dis[i] = rsqrtf((float)(d + 1));
    red[t] = d;
    __syncthreads();
    for (int off = 128; off > 0; off >>= 1) {
        if (t < off) red[t] += red[t + off];
        __syncthreads();
    }
    if (t == 0) g_bsum[blockIdx.x] = red[0];
}
__global__ void k_scan_b() {
    __shared__ int s[256];
    int t = threadIdx.x;
    int v = (t < SCANB) ? g_bsum[t] : 0;
    s[t] = v;
    __syncthreads();
    for (int off = 1; off < 256; off <<= 1) {
        int u = (t >= off) ? s[t - off] : 0;
        __syncthreads();
        s[t] += u;
        __syncthreads();
    }
    if (t < SCANB) g_bpre[t] = s[t] - v;
}
__global__ void k_scan_c() {
    __shared__ int s[256];
    int t = threadIdx.x;
    int i = blockIdx.x * 256 + t;
    int d = (i < NNODES) ? g_deg[i] : 0;
    s[t] = d;
    __syncthreads();
    for (int off = 1; off < 256; off <<= 1) {
        int u = (t >= off) ? s[t - off] : 0;
        __syncthreads();
        s[t] += u;
        __syncthreads();
    }
    if (i < NNODES) {
        int excl = s[t] - d + g_bpre[blockIdx.x];
        g_rowoff[i] = excl;
        g_cursor[i] = excl;
    }
}

// ---------------- CSR bucket scatter ----------------
__global__ void k_scatter(const int* __restrict__ e) {
    int i = blockIdx.x * blockDim.x + threadIdx.x;
    int is64 = g_is64;
    if (i < NEDGES) {
        int s = edge_at(e, i, is64);
        int d = edge_at(e, NEDGES + i, is64);
        g_csr[atomicAdd(&g_cursor[d], 1)] = s;
    }
}

// ---------------- shared mma compute/epilogue ----------------
__device__ __forceinline__ void compute_k32(uint32_t bAh, uint32_t bAl, uint32_t bBh,
                                            uint32_t bBl, float (&acc)[2][8][4],
                                            int wm, int wn, int l) {
    int a_r = (l & 7) + ((l >> 3) & 1) * 8;
    int a_c = ((l >> 4) & 1) * 8;
    int b_n = (l & 7) + ((l >> 4) & 1) * 8;
    int b_k = ((l >> 3) & 1) * 8;
#pragma unroll
    for (int kk = 0; kk < 32; kk += 16) {
        uint32_t ah[2][4], al[2][4];
#pragma unroll
        for (int mi = 0; mi < 2; mi++) {
            int r = wm * 32 + mi * 16 + a_r;
            uint32_t off = (uint32_t)(r * (ASTRIDE * 2) + (kk + a_c) * 2);
            LDSM_X4(ah[mi], bAh + off);
            LDSM_X4(al[mi], bAl + off);
        }
#pragma unroll
        for (int ng = 0; ng < 4; ng++) {
            uint32_t bh[4], bl[4];
            int nr = wn * 64 + ng * 16 + b_n;
            uint32_t off = (uint32_t)(nr * (ASTRIDE * 2) + (kk + b_k) * 2);
            LDSM_X4(bh, bBh + off);
            LDSM_X4(bl, bBl + off);
#pragma unroll
            for (int mi = 0; mi < 2; mi++) {
                MMA_BF16(acc[mi][ng * 2 + 0], ah[mi], bh[0], bh[1]);
                MMA_BF16(acc[mi][ng * 2 + 0], ah[mi], bl[0], bl[1]);
                MMA_BF16(acc[mi][ng * 2 + 0], al[mi], bh[0], bh[1]);
                MMA_BF16(acc[mi][ng * 2 + 1], ah[mi], bh[2], bh[3]);
                MMA_BF16(acc[mi][ng * 2 + 1], ah[mi], bl[2], bl[3]);
                MMA_BF16(acc[mi][ng * 2 + 1], al[mi], bh[2], bh[3]);
            }
        }
    }
}
__device__ __forceinline__ void epilogue(float* __restrict__ C, int NT, int m0, int n0,
                                         float (&acc)[2][8][4], int wm, int wn, int l) {
#pragma unroll
    for (int mi = 0; mi < 2; mi++) {
#pragma unroll
        for (int ni = 0; ni < 8; ni++) {
            int r = m0 + wm * 32 + mi * 16 + (l >> 2);
            int cc = n0 + wn * 64 + ni * 8 + (l & 3) * 2;
            if (r < NNODES)
                *(float2*)(C + (size_t)r * NT + cc) = make_float2(acc[mi][ni][0], acc[mi][ni][1]);
            if (r + 8 < NNODES)
                *(float2*)(C + (size_t)(r + 8) * NT + cc) = make_float2(acc[mi][ni][2], acc[mi][ni][3]);
        }
    }
}

// ---------------- GEMM1: pre-split bf16 A (x) and B (W1^T) ----------------
__global__ __launch_bounds__(256) void k_gemm1() {
    __shared__ __align__(16) __nv_bfloat16 As_h[128 * ASTRIDE];
    __shared__ __align__(16) __nv_bfloat16 As_l[128 * ASTRIDE];
    __shared__ __align__(16) __nv_bfloat16 Bs_h[128 * ASTRIDE];
    __shared__ __align__(16) __nv_bfloat16 Bs_l[128 * ASTRIDE];
    int tid = threadIdx.x, wid = tid >> 5, l = tid & 31;
    int m0 = blockIdx.y * 128, n0 = blockIdx.x * 128;
    int wm = wid & 3, wn = wid >> 2;
    uint32_t bAh = smem_u32(As_h), bAl = smem_u32(As_l);
    uint32_t bBh = smem_u32(Bs_h), bBl = smem_u32(Bs_l);

    int row = tid >> 1, half = (tid & 1) * 16;   // 16 bf16 elements per thread
    int gr = m0 + row; if (gr > NNODES - 1) gr = NNODES - 1;
    const __nv_bfloat16* Ah = g_xh + (size_t)gr * INDIM + half;
    const __nv_bfloat16* Al = g_xl + (size_t)gr * INDIM + half;
    const __nv_bfloat16* Bh = g_w1ht + (size_t)(n0 + row) * INDIM + half;
    const __nv_bfloat16* Bl = g_w1lt + (size_t)(n0 + row) * INDIM + half;
    int soff = row * ASTRIDE + half;

    float acc[2][8][4];
#pragma unroll
    for (int a = 0; a < 2; a++)
#pragma unroll
        for (int b = 0; b < 8; b++)
#pragma unroll
            for (int c = 0; c < 4; c++) acc[a][b][c] = 0.f;

    for (int k0 = 0; k0 < INDIM; k0 += 32) {
        // 16 bf16 = 32 bytes = 2 x uint4 per thread per tile
        *(uint4*)(As_h + soff)     = *(const uint4*)(Ah + k0);
        *(uint4*)(As_h + soff + 8) = *(const uint4*)(Ah + k0 + 8);
        *(uint4*)(As_l + soff)     = *(const uint4*)(Al + k0);
        *(uint4*)(As_l + soff + 8) = *(const uint4*)(Al + k0 + 8);
        *(uint4*)(Bs_h + soff)     = *(const uint4*)(Bh + k0);
        *(uint4*)(Bs_h + soff + 8) = *(const uint4*)(Bh + k0 + 8);
        *(uint4*)(Bs_l + soff)     = *(const uint4*)(Bl + k0);
        *(uint4*)(Bs_l + soff + 8) = *(const uint4*)(Bl + k0 + 8);
        __syncthreads();
        compute_k32(bAh, bAl, bBh, bBl, acc, wm, wn, l);
        __syncthreads();
    }
    epilogue(g_h1, DD1, m0, n0, acc, wm, wn, l);
}

// ---------------- GEMM2: fp32 A (agg1, BN1+ReLU fused+split) x pre-split B (W2^T) ----------------
__global__ __launch_bounds__(256) void k_gemm2() {
    __shared__ __align__(16) __nv_bfloat16 As_h[128 * ASTRIDE];
    __shared__ __align__(16) __nv_bfloat16 As_l[128 * ASTRIDE];
    __shared__ __align__(16) __nv_bfloat16 Bs_h[128 * ASTRIDE];
    __shared__ __align__(16) __nv_bfloat16 Bs_l[128 * ASTRIDE];
    int tid = threadIdx.x, wid = tid >> 5, l = tid & 31;
    int m0 = blockIdx.y * 128, n0 = 0;
    int wm = wid & 3, wn = wid >> 2;
    uint32_t bAh = smem_u32(As_h), bAl = smem_u32(As_l);
    uint32_t bBh = smem_u32(Bs_h), bBl = smem_u32(Bs_l);

    int row = tid >> 1;
    int half = (tid & 1) * 16;
    int gr = m0 + row; if (gr > NNODES - 1) gr = NNODES - 1;
    const float* Arow = g_agg1 + (size_t)gr * DD1;
    const __nv_bfloat16* Bh = g_w2ht + (size_t)(n0 + row) * DD1 + half;
    const __nv_bfloat16* Bl = g_w2lt + (size_t)(n0 + row) * DD1 + half;
    int soff = row * ASTRIDE + half;

    float acc[2][8][4];
#pragma unroll
    for (int a = 0; a < 2; a++)
#pragma unroll
        for (int b = 0; b < 8; b++)
#pragma unroll
            for (int c = 0; c < 4; c++) acc[a][b][c] = 0.f;

    for (int k0 = 0; k0 < DD1; k0 += 32) {
#pragma unroll
        for (int q = 0; q < 4; q++) {
            int c = half + q * 4;
            float4 v = *(const float4*)(Arow + k0 + c);
            int cc = k0 + c;
            v.x = fmaxf(fmaf(v.x, g_scale1[cc + 0], g_shift1[cc + 0]), 0.f);
            v.y = fmaxf(fmaf(v.y, g_scale1[cc + 1], g_shift1[cc + 1]), 0.f);
            v.z = fmaxf(fmaf(v.z, g_scale1[cc + 2], g_shift1[cc + 2]), 0.f);
            v.w = fmaxf(fmaf(v.w, g_scale1[cc + 3], g_shift1[cc + 3]), 0.f);
            float r0, r1, r2, r3;
            uint32_t h01 = pack_split(v.x, v.y, r0, r1);
            uint32_t h23 = pack_split(v.z, v.w, r2, r3);
            int off = row * ASTRIDE + c;
            *(uint2*)(As_h + off) = make_uint2(h01, h23);
            *(uint2*)(As_l + off) = make_uint2(pack_bf2(r0, r1), pack_bf2(r2, r3));
        }
        *(uint4*)(Bs_h + soff)     = *(const uint4*)(Bh + k0);
        *(uint4*)(Bs_h + soff + 8) = *(const uint4*)(Bh + k0 + 8);
        *(uint4*)(Bs_l + soff)     = *(const uint4*)(Bl + k0);
        *(uint4*)(Bs_l + soff + 8) = *(const uint4*)(Bl + k0 + 8);
        __syncthreads();
        compute_k32(bAh, bAl, bBh, bBl, acc, wm, wn, l);
        __syncthreads();
    }
    epilogue(g_h2, DD2, m0, n0, acc, wm, wn, l);
}

// ---------------- warp-per-node gather aggregation (float4 + shfl) ----------------
template <int DIM>
__global__ void k_aggw(const float* __restrict__ H, float* __restrict__ O) {
    int warp = (blockIdx.x * blockDim.x + threadIdx.x) >> 5;
    int lane = threadIdx.x & 31;
    if (warp >= NNODES) return;
    int d = warp;
    float dd = g_dis[d];
    constexpr int V = DIM / 128;   // float4 per lane: DD1->2, DD2->1
    const float4* Hd = (const float4*)(H + (size_t)d * DIM);
    float4 acc[V];
#pragma unroll
    for (int v = 0; v < V; v++) {
        float4 x = Hd[lane + 32 * v];
        acc[v] = make_float4(dd * x.x, dd * x.y, dd * x.z, dd * x.w);
    }
    int beg = g_rowoff[d], end = g_rowoff[d + 1];
    for (int base = beg; base < end; base += 32) {
        int cnt = min(end - base, 32);
        int s = 0; float w = 0.f;
        if (lane < cnt) {
            s = g_csr[base + lane];
            w = g_dis[s];
        }
        for (int j = 0; j < cnt; j++) {
            int sj = __shfl_sync(0xffffffffu, s, j);
            float wj = __shfl_sync(0xffffffffu, w, j);
            const float4* R = (const float4*)(H + (size_t)sj * DIM);
#pragma unroll
            for (int v = 0; v < V; v++) {
                float4 x = R[lane + 32 * v];
                acc[v].x = fmaf(wj, x.x, acc[v].x);
                acc[v].y = fmaf(wj, x.y, acc[v].y);
                acc[v].z = fmaf(wj, x.z, acc[v].z);
                acc[v].w = fmaf(wj, x.w, acc[v].w);
            }
        }
    }
    float4* Od = (float4*)(O + (size_t)d * DIM);
#pragma unroll
    for (int v = 0; v < V; v++)
        Od[lane + 32 * v] = make_float4(acc[v].x * dd, acc[v].y * dd, acc[v].z * dd, acc[v].w * dd);
}

// ---------------- BN stats ----------------
template <int DIM>
__device__ __forceinline__ void bnstats_impl(const float* __restrict__ X,
                                             float* __restrict__ sum, float* __restrict__ sq) {
    int t = threadIdx.x;
    int r0 = blockIdx.x * 64;
    int r1 = min(r0 + 64, NNODES);
    float s = 0.f, q = 0.f;
    for (int r = r0; r < r1; r++) {
        float v = X[(size_t)r * DIM + t];
        s += v;
        q += v * v;
    }
    atomicAdd(&sum[t], s);
    atomicAdd(&sq[t], q);
}
__global__ void k_bnstats1() { bnstats_impl<DD1>(g_agg1, g_sum1, g_sq1); }
__global__ void k_bnstats2() { bnstats_impl<DD2>(g_agg2, g_sum2, g_sq2); }

template <int DIM>
__device__ __forceinline__ void finalize_impl(const float* __restrict__ sum,
                                              const float* __restrict__ sq,
                                              const float* __restrict__ gamma,
                                              const float* __restrict__ beta,
                                              float* __restrict__ scale,
                                              float* __restrict__ shift) {
    int t = threadIdx.x;
    float mean = sum[t] * (1.f / NNODES);
    float var = fmaxf(sq[t] * (1.f / NNODES) - mean * mean, 0.f);
    float sc = rsqrtf(var + FEPS) * gamma[t];
    scale[t] = sc;
    shift[t] = beta[t] - mean * sc;
}
__global__ void k_finalize1(const float* g, const float* b) {
    finalize_impl<DD1>(g_sum1, g_sq1, g, b, g_scale1, g_shift1);
}
__global__ void k_finalize2(const float* g, const float* b) {
    finalize_impl<DD2>(g_sum2, g_sq2, g, b, g_scale2, g_shift2);
}

// ---------------- final BN2 apply -> d_out ----------------
__global__ void k_apply(float* __restrict__ out) {
    int i = blockIdx.x * blockDim.x + threadIdx.x;
    if (i < NNODES * DD2) {
        int c = i & (DD2 - 1);
        out[i] = g_agg2[i] * g_scale2[c] + g_shift2[c];
    }
}

// ---------------- launch ----------------
extern "C" void kernel_launch(void* const* d_in, const int* in_sizes, int n_in,
                              void* d_out, int out_size) {
    const float* x      = (const float*)d_in[0];
    const int*   e      = (const int*)d_in[1];
    const float* W1     = (const float*)d_in[2];
    const float* gamma1 = (const float*)d_in[4];
    const float* beta1  = (const float*)d_in[5];
    const float* W2     = (const float*)d_in[6];
    const float* gamma2 = (const float*)d_in[8];
    const float* beta2  = (const float*)d_in[9];
    float* out = (float*)d_out;

    void *p_h1, *p_agg1, *p_h2, *p_agg2;
    cudaGetSymbolAddress(&p_h1, g_h1);
    cudaGetSymbolAddress(&p_agg1, g_agg1);
    cudaGetSymbolAddress(&p_h2, g_h2);
    cudaGetSymbolAddress(&p_agg2, g_agg2);

    const int EG = (NEDGES + 255) / 256;
    const int MB = (NNODES + 127) / 128;   // 391
    const int AGG_G = (NNODES * 32 + 255) / 256;  // warp-per-node

    k_init<<<(NNODES + 255) / 256, 256>>>(e);
    k_split_x<<<(NNODES * INDIM / 4 + 255) / 256, 256>>>(x);
    k_split_w1<<<(DD1 * INDIM + 255) / 256, 256>>>(W1);
    k_split_w2<<<(DD2 * DD1 + 255) / 256, 256>>>(W2);

    k_degree<<<EG, 256>>>(e);
    k_scan_a<<<SCANB, 256>>>();
    k_scan_b<<<1, 256>>>();
    k_scan_c<<<SCANB, 256>>>();
    k_scatter<<<EG, 256>>>(e);

    k_gemm1<<<dim3(2, MB), 256>>>();
    k_aggw<DD1><<<AGG_G, 256>>>((const float*)p_h1, (float*)p_agg1);
    k_bnstats1<<<(NNODES + 63) / 64, DD1>>>();
    k_finalize1<<<1, DD1>>>(gamma1, beta1);

    k_gemm2<<<dim3(1, MB), 256>>>();
    k_aggw<DD2><<<AGG_G, 256>>>((const float*)p_h2, (float*)p_agg2);
    k_bnstats2<<<(NNODES + 63) / 64, DD2>>>();
    k_finalize2<<<1, DD2>>>(gamma2, beta2);

    k_apply<<<(NNODES * DD2 + 255) / 256, 256>>>(out);
}